// round 1
// baseline (speedup 1.0000x reference)
#include <cuda_runtime.h>

// ---------------------------------------------------------------------------
// 2-level 3D inverse DWT (db4, mode='zero').
//
// Key identity: _sfb1d (lhs_dilated conv, pad (1,1), flipped kernel, L=8) is
// conv_transpose(stride=2, padding=6). Output length M = 2n-6, and every
// output is exactly 4 taps per band:
//   y[2p]   = sum_t x[p+t] * g[6-2t]
//   y[2p+1] = sum_t x[p+t] * g[7-2t]
// (no boundary clipping anywhere for these sizes).
//
// Staged implementation: per level, 3 passes (axis -1, -2, -3) halving band
// count each time. Scratch lives in __device__ globals (no allocations).
// ---------------------------------------------------------------------------

// db4 reconstruction low-pass g0; high-pass g1[j] = (-1)^j g0[7-j].
// Even-output taps use g[6],g[4],g[2],g[0]; odd use g[7],g[5],g[3],g[1].
#define G0_0 0.23037781330885523f
#define G0_1 0.7148465705525415f
#define G0_2 0.6308807679295904f
#define G0_3 (-0.02798376941698385f)
#define G0_4 (-0.18703481171888114f)
#define G0_5 0.030841381835986965f
#define G0_6 0.032883011666982945f
#define G0_7 (-0.010597401784997278f)

#define G1_0 (-0.010597401784997278f)   // +g0[7]
#define G1_1 (-0.032883011666982945f)   // -g0[6]
#define G1_2 0.030841381835986965f      // +g0[5]
#define G1_3 0.18703481171888114f       // -g0[4]
#define G1_4 (-0.02798376941698385f)    // +g0[3]
#define G1_5 (-0.6308807679295904f)     // -g0[2]
#define G1_6 0.7148465705525415f        // +g0[1]
#define G1_7 (-0.23037781330885523f)    // -g0[0]

__device__ __forceinline__ void sfb_pair(
    float l0, float l1, float l2, float l3,
    float h0, float h1, float h2, float h3,
    float& ye, float& yo)
{
    // even: lo taps g0[6],g0[4],g0[2],g0[0]; hi taps g1[6],g1[4],g1[2],g1[0]
    ye = fmaf(l0, G0_6,
         fmaf(l1, G0_4,
         fmaf(l2, G0_2,
         fmaf(l3, G0_0,
         fmaf(h0, G1_6,
         fmaf(h1, G1_4,
         fmaf(h2, G1_2,
              h3 * G1_0)))))));
    // odd: lo taps g0[7],g0[5],g0[3],g0[1]; hi taps g1[7],g1[5],g1[3],g1[1]
    yo = fmaf(l0, G0_7,
         fmaf(l1, G0_5,
         fmaf(l2, G0_3,
         fmaf(l3, G0_1,
         fmaf(h0, G1_7,
         fmaf(h1, G1_5,
         fmaf(h2, G1_3,
              h3 * G1_1)))))));
}

// Scratch (device globals; sized for level 2, reused by level 1):
//   A: 64 groups x (66*66*126) = 35,126,784 floats (140.5 MB)
//   B: 32 groups x (66*126*126) = 33,530,112 floats (134.1 MB)
//   LL1: level-1 output, 16 x 66^3 = 4,599,936 floats (18.4 MB)
__device__ float g_scratchA[35126784];
__device__ float g_scratchB[33530112];
__device__ float g_LL1[4599936];

// ---------------------------------------------------------------------------
// Stage A: transform along last (contiguous) axis.
// Bands come from two tensors: low band (j==0 lo) from `yl`, high bands from
// `yh` laid out [slice][7][n][n][n]. Output A laid out [g = slice*4+j][n][n][M].
// ---------------------------------------------------------------------------
__global__ void k_stageA(const float* __restrict__ yl,
                         const float* __restrict__ yh,
                         float* __restrict__ out,
                         int n, long long total)
{
    long long tid = (long long)blockIdx.x * blockDim.x + threadIdx.x;
    if (tid >= total) return;

    const int npairs = n - 3;
    const int M = 2 * n - 6;

    int p = (int)(tid % npairs);
    long long r = tid / npairs;
    int y = (int)(r % n); r /= n;
    int z = (int)(r % n); r /= n;
    int g = (int)r;                 // slice*4 + j
    int slice = g >> 2;
    int j = g & 3;

    long long vol = (long long)n * n * n;
    const float* lo = (j == 0) ? (yl + (long long)slice * vol)
                               : (yh + ((long long)slice * 7 + (2 * j - 1)) * vol);
    const float* hi = yh + ((long long)slice * 7 + 2 * j) * vol;

    long long base = ((long long)z * n + y) * n + p;
    float l0 = lo[base],     l1 = lo[base + 1], l2 = lo[base + 2], l3 = lo[base + 3];
    float h0 = hi[base],     h1 = hi[base + 1], h2 = hi[base + 2], h3 = hi[base + 3];

    float ye, yo;
    sfb_pair(l0, l1, l2, l3, h0, h1, h2, h3, ye, yo);

    long long obase = (((long long)g * n + z) * n + y) * M + 2 * p;
    out[obase]     = ye;
    out[obase + 1] = yo;
}

// ---------------------------------------------------------------------------
// Generic strided stage (axes -2 and -3): each group is a (lo, hi) slab pair;
// slab layout (outer, n, inner); output layout (outer, M, inner).
// ---------------------------------------------------------------------------
__global__ void k_stageS(const float* __restrict__ in,
                         float* __restrict__ out,
                         int n, int outer, long long inner,
                         long long hi_off, long long gin_stride, long long gout_stride,
                         long long total)
{
    long long tid = (long long)blockIdx.x * blockDim.x + threadIdx.x;
    if (tid >= total) return;

    const int npairs = n - 3;
    const int M = 2 * n - 6;

    long long ix = tid % inner;
    long long r = tid / inner;
    int p = (int)(r % npairs); r /= npairs;
    int o = (int)(r % outer);  r /= outer;
    int g = (int)r;

    const float* lo = in + (long long)g * gin_stride + ((long long)o * n + p) * inner + ix;
    const float* hi = lo + hi_off;
    const long long s = inner;  // stride along transform axis

    float l0 = lo[0], l1 = lo[s], l2 = lo[2 * s], l3 = lo[3 * s];
    float h0 = hi[0], h1 = hi[s], h2 = hi[2 * s], h3 = hi[3 * s];

    float ye, yo;
    sfb_pair(l0, l1, l2, l3, h0, h1, h2, h3, ye, yo);

    float* op = out + (long long)g * gout_stride + ((long long)o * M + 2 * p) * inner + ix;
    op[0]     = ye;
    op[inner] = yo;
}

static inline int cdiv_ll(long long a, int b) { return (int)((a + b - 1) / b); }

extern "C" void kernel_launch(void* const* d_in, const int* in_sizes, int n_in,
                              void* d_out, int out_size)
{
    (void)in_sizes; (void)n_in; (void)out_size;

    const float* yl  = (const float*)d_in[0];  // (2,8,36,36,36)
    const float* yh0 = (const float*)d_in[1];  // (2,8,7,66,66,66)
    const float* yh1 = (const float*)d_in[2];  // (2,8,7,36,36,36)
    float* out = (float*)d_out;                // (2,8,126,126,126)

    float *A, *B, *LL1;
    cudaGetSymbolAddress((void**)&A,   g_scratchA);
    cudaGetSymbolAddress((void**)&B,   g_scratchB);
    cudaGetSymbolAddress((void**)&LL1, g_LL1);

    const int TPB = 256;

    // ---------------- Level 1: n=36 -> 66, bands yl + yh1 ----------------
    {
        const int n = 36, M = 66, np = n - 3;
        const long long volA = (long long)n * n * M;       // per-band slab after stage A
        const long long volB = (long long)n * M * M;       // per-band slab after stage B

        long long totA = 64LL * n * n * np;
        k_stageA<<<cdiv_ll(totA, TPB), TPB>>>(yl, yh1, A, n, totA);

        long long totB = 32LL * n * np * M;
        k_stageS<<<cdiv_ll(totB, TPB), TPB>>>(A, B, n, /*outer*/n, /*inner*/M,
                                              /*hi_off*/volA, /*gin*/2 * volA,
                                              /*gout*/volB, totB);

        long long totC = 16LL * np * (long long)M * M;
        k_stageS<<<cdiv_ll(totC, TPB), TPB>>>(B, LL1, n, /*outer*/1, /*inner*/(long long)M * M,
                                              /*hi_off*/volB, /*gin*/2 * volB,
                                              /*gout*/(long long)M * M * M, totC);
    }

    // ---------------- Level 2: n=66 -> 126, bands LL1 + yh0 ----------------
    {
        const int n = 66, M = 126, np = n - 3;
        const long long volA = (long long)n * n * M;
        const long long volB = (long long)n * M * M;

        long long totA = 64LL * n * n * np;
        k_stageA<<<cdiv_ll(totA, TPB), TPB>>>(LL1, yh0, A, n, totA);

        long long totB = 32LL * n * np * M;
        k_stageS<<<cdiv_ll(totB, TPB), TPB>>>(A, B, n, /*outer*/n, /*inner*/M,
                                              /*hi_off*/volA, /*gin*/2 * volA,
                                              /*gout*/volB, totB);

        long long totC = 16LL * np * (long long)M * M;
        k_stageS<<<cdiv_ll(totC, TPB), TPB>>>(B, out, n, /*outer*/1, /*inner*/(long long)M * M,
                                              /*hi_off*/volB, /*gin*/2 * volB,
                                              /*gout*/(long long)M * M * M, totC);
    }
}